// round 7
// baseline (speedup 1.0000x reference)
#include <cuda_runtime.h>
#include <math.h>

// Shapes (fixed by the problem)
#define Bc 4
#define Hc 16
#define Sc 1024
#define Dc 64

// Tiling
#define BQ 64
#define BKT 64
#define DPAD 68      // 64 + 4 pad (floats) — float4-aligned rows, breaks bank patterns
#define BKPAD 68
#define NTHREADS 256

// Mask layout flag: 0 = 32-bit words (int32 or float32 bool), 1 = 1-byte bools
__device__ int g_mask_byte_mode;

__global__ void detect_mask_dtype_kernel(const unsigned int* __restrict__ m) {
    __shared__ int bad;
    if (threadIdx.x == 0) bad = 0;
    __syncthreads();
    // Scan 8192 words (32KB). Safe for any candidate layout (buffer >= 64MB).
    // int32 bools  -> words in {0,1}
    // float32 bools-> words in {0, 0x3F800000}
    // u8 bools     -> packed words like 0x01010101 appear w.p. 7/8 per word
    int local_bad = 0;
    for (int i = threadIdx.x; i < 8192; i += blockDim.x) {
        unsigned int w = m[i];
        if (w != 0u && w != 1u && w != 0x3F800000u) local_bad = 1;
    }
    if (local_bad) bad = 1;
    __syncthreads();
    if (threadIdx.x == 0) g_mask_byte_mode = bad;
}

__global__ __launch_bounds__(NTHREADS, 2)
void attn_flash_kernel(const float* __restrict__ Q,
                       const float* __restrict__ K,
                       const float* __restrict__ V,
                       const void* __restrict__ MSK,
                       const float* __restrict__ TW,
                       const float* __restrict__ DU,
                       float* __restrict__ O) {
    extern __shared__ float sm[];
    float* sQ = sm;                          // BQ  x DPAD
    float* sK = sQ + BQ * DPAD;              // BKT x DPAD
    float* sV = sK + BKT * DPAD;             // BKT x DPAD
    float* sP = sV + BKT * DPAD;             // BQ  x BKPAD (scores -> weights)
    float* sMx = sP + BQ * BKPAD;            // BQ running max
    float* sZ  = sMx + BQ;                   // BQ running denom
    float* sC  = sZ + BQ;                    // BQ correction factor

    const int t  = threadIdx.x;
    const int bh = blockIdx.x >> 4;          // Sc/BQ == 16 q-tiles
    const int qt = blockIdx.x & 15;
    const int q0 = qt * BQ;

    const int mask_bytes = g_mask_byte_mode; // uniform across grid

    const size_t qkvbase = (size_t)bh * Sc * Dc;
    const size_t mbase   = (size_t)bh * Sc * Sc;
    const float* Qb = Q + qkvbase;
    const float* Kb = K + qkvbase;
    const float* Vb = V + qkvbase;
    const unsigned int*  MbW = (const unsigned int*)MSK + mbase;   // word bools
    const unsigned char* MbB = (const unsigned char*)MSK + mbase;  // byte bools
    const float* Tb = TW + mbase;
    const float* Ub = DU + mbase;
    float* Ob = O + qkvbase;

    // ---- Load Q tile (coalesced float4) ----
    for (int i = t; i < BQ * (Dc / 4); i += NTHREADS) {
        int q = i >> 4, d4 = i & 15;
        ((float4*)(sQ + q * DPAD))[d4] =
            ((const float4*)(Qb + (size_t)(q0 + q) * Dc))[d4];
    }
    if (t < BQ) { sMx[t] = -INFINITY; sZ[t] = 0.f; }

    // Phase-D / epilogue thread mapping: thread owns query aq, float4 chunks
    // at d4 = ql + 4*i (interleaved -> conflict-free sV reads)
    const int aq = t >> 2;
    const int ql = t & 3;
    float4 a0 = make_float4(0.f, 0.f, 0.f, 0.f);
    float4 a1 = a0, a2 = a0, a3 = a0;

    // Phase-A mapping: 4x4 micro-tile, q rows tq..tq+3, k cols u+16j (striped)
    const int tq = (t >> 4) << 2;            // 0,4,...,60
    const int u  = t & 15;

    __syncthreads();

    const float scale = 0.125f;              // 1/sqrt(64)

    for (int kt = 0; kt < Sc / BKT; kt++) {
        const int k0 = kt * BKT;

        // ---- Load K,V tiles ----
        for (int i = t; i < BKT * (Dc / 4); i += NTHREADS) {
            int k = i >> 4, d4 = i & 15;
            ((float4*)(sK + k * DPAD))[d4] =
                ((const float4*)(Kb + (size_t)(k0 + k) * Dc))[d4];
            ((float4*)(sV + k * DPAD))[d4] =
                ((const float4*)(Vb + (size_t)(k0 + k) * Dc))[d4];
        }
        __syncthreads();

        // ---- Phase A: S = Q K^T (4x4 micro-tile per thread) ----
        {
            float s00=0,s01=0,s02=0,s03=0, s10=0,s11=0,s12=0,s13=0;
            float s20=0,s21=0,s22=0,s23=0, s30=0,s31=0,s32=0,s33=0;
            #pragma unroll 4
            for (int d4 = 0; d4 < 16; d4++) {
                float4 q0v = ((const float4*)(sQ + (tq + 0) * DPAD))[d4];
                float4 q1v = ((const float4*)(sQ + (tq + 1) * DPAD))[d4];
                float4 q2v = ((const float4*)(sQ + (tq + 2) * DPAD))[d4];
                float4 q3v = ((const float4*)(sQ + (tq + 3) * DPAD))[d4];
                float4 k0v = ((const float4*)(sK + (u +  0) * DPAD))[d4];
                float4 k1v = ((const float4*)(sK + (u + 16) * DPAD))[d4];
                float4 k2v = ((const float4*)(sK + (u + 32) * DPAD))[d4];
                float4 k3v = ((const float4*)(sK + (u + 48) * DPAD))[d4];
                s00 += q0v.x*k0v.x + q0v.y*k0v.y + q0v.z*k0v.z + q0v.w*k0v.w;
                s01 += q0v.x*k1v.x + q0v.y*k1v.y + q0v.z*k1v.z + q0v.w*k1v.w;
                s02 += q0v.x*k2v.x + q0v.y*k2v.y + q0v.z*k2v.z + q0v.w*k2v.w;
                s03 += q0v.x*k3v.x + q0v.y*k3v.y + q0v.z*k3v.z + q0v.w*k3v.w;
                s10 += q1v.x*k0v.x + q1v.y*k0v.y + q1v.z*k0v.z + q1v.w*k0v.w;
                s11 += q1v.x*k1v.x + q1v.y*k1v.y + q1v.z*k1v.z + q1v.w*k1v.w;
                s12 += q1v.x*k2v.x + q1v.y*k2v.y + q1v.z*k2v.z + q1v.w*k2v.w;
                s13 += q1v.x*k3v.x + q1v.y*k3v.y + q1v.z*k3v.z + q1v.w*k3v.w;
                s20 += q2v.x*k0v.x + q2v.y*k0v.y + q2v.z*k0v.z + q2v.w*k0v.w;
                s21 += q2v.x*k1v.x + q2v.y*k1v.y + q2v.z*k1v.z + q2v.w*k1v.w;
                s22 += q2v.x*k2v.x + q2v.y*k2v.y + q2v.z*k2v.z + q2v.w*k2v.w;
                s23 += q2v.x*k3v.x + q2v.y*k3v.y + q2v.z*k3v.z + q2v.w*k3v.w;
                s30 += q3v.x*k0v.x + q3v.y*k0v.y + q3v.z*k0v.z + q3v.w*k0v.w;
                s31 += q3v.x*k1v.x + q3v.y*k1v.y + q3v.z*k1v.z + q3v.w*k1v.w;
                s32 += q3v.x*k2v.x + q3v.y*k2v.y + q3v.z*k2v.z + q3v.w*k2v.w;
                s33 += q3v.x*k3v.x + q3v.y*k3v.y + q3v.z*k3v.z + q3v.w*k3v.w;
            }
            float sv[4][4] = {{s00,s01,s02,s03},{s10,s11,s12,s13},
                              {s20,s21,s22,s23},{s30,s31,s32,s33}};
            if (mask_bytes == 0) {
                // int32 / float32 bool: nonzero word == masked
                #pragma unroll
                for (int i = 0; i < 4; i++) {
                    const unsigned int* mrow = MbW + (size_t)(q0 + tq + i) * Sc + k0;
                    float* prow = sP + (tq + i) * BKPAD;
                    #pragma unroll
                    for (int j = 0; j < 4; j++) {
                        int k = u + 16 * j;
                        prow[k] = mrow[k] ? -1e9f : sv[i][j] * scale;
                    }
                }
            } else {
                // 1-byte bool
                #pragma unroll
                for (int i = 0; i < 4; i++) {
                    const unsigned char* mrow = MbB + (size_t)(q0 + tq + i) * Sc + k0;
                    float* prow = sP + (tq + i) * BKPAD;
                    #pragma unroll
                    for (int j = 0; j < 4; j++) {
                        int k = u + 16 * j;
                        prow[k] = mrow[k] ? -1e9f : sv[i][j] * scale;
                    }
                }
            }
        }
        __syncthreads();

        // ---- Phase B: per-row tile max, combine with running max ----
        {
            int r = t >> 2;
            float mx = -INFINITY;
            #pragma unroll
            for (int k = ql; k < BKT; k += 4) mx = fmaxf(mx, sP[r * BKPAD + k]);
            mx = fmaxf(mx, __shfl_xor_sync(0xffffffffu, mx, 1));
            mx = fmaxf(mx, __shfl_xor_sync(0xffffffffu, mx, 2));
            if (ql == 0) {
                float mold = sMx[r];
                float mnew = fmaxf(mold, mx);
                sMx[r] = mnew;
                sC[r]  = __expf(mold - mnew);   // 0 on first tile (mold=-inf)
            }
        }
        __syncthreads();

        // ---- Phase C: p=exp(s-m); Z update; fold tw * dropout into P ----
        // warp w owns rows 8w..8w+7; lanes stride k -> coalesced tw/du loads
        {
            int w = t >> 5, lane = t & 31;
            #pragma unroll
            for (int r8 = 0; r8 < 8; r8++) {
                int r = (w << 3) + r8;
                float mnew = sMx[r];
                const float* trow = Tb + (size_t)(q0 + r) * Sc + k0;
                const float* urow = Ub + (size_t)(q0 + r) * Sc + k0;
                float sum = 0.f;
                #pragma unroll
                for (int h = 0; h < 2; h++) {
                    int k = lane + 32 * h;
                    float p = __expf(sP[r * BKPAD + k] - mnew);
                    sum += p;
                    float keep = (urow[k] >= 0.5f) ? 2.0f : 0.0f;
                    sP[r * BKPAD + k] = p * trow[k] * keep;
                }
                #pragma unroll
                for (int off = 16; off; off >>= 1)
                    sum += __shfl_xor_sync(0xffffffffu, sum, off);
                if (lane == 0) sZ[r] = sZ[r] * sC[r] + sum;
            }
        }
        __syncthreads();

        // ---- Phase D: acc = acc*c + P_w @ V ----
        {
            float c = sC[aq];
            a0.x*=c; a0.y*=c; a0.z*=c; a0.w*=c;
            a1.x*=c; a1.y*=c; a1.z*=c; a1.w*=c;
            a2.x*=c; a2.y*=c; a2.z*=c; a2.w*=c;
            a3.x*=c; a3.y*=c; a3.z*=c; a3.w*=c;
            const float* prow = sP + aq * BKPAD;
            #pragma unroll 4
            for (int k = 0; k < BKT; k++) {
                float p = prow[k];
                const float4* vr = (const float4*)(sV + k * DPAD);
                float4 v;
                v = vr[ql +  0]; a0.x += p*v.x; a0.y += p*v.y; a0.z += p*v.z; a0.w += p*v.w;
                v = vr[ql +  4]; a1.x += p*v.x; a1.y += p*v.y; a1.z += p*v.z; a1.w += p*v.w;
                v = vr[ql +  8]; a2.x += p*v.x; a2.y += p*v.y; a2.z += p*v.z; a2.w += p*v.w;
                v = vr[ql + 12]; a3.x += p*v.x; a3.y += p*v.y; a3.z += p*v.z; a3.w += p*v.w;
            }
        }
        __syncthreads();
    }

    // ---- Epilogue: out = acc / Z ----
    {
        float inv = 1.0f / sZ[aq];
        a0.x*=inv; a0.y*=inv; a0.z*=inv; a0.w*=inv;
        a1.x*=inv; a1.y*=inv; a1.z*=inv; a1.w*=inv;
        a2.x*=inv; a2.y*=inv; a2.z*=inv; a2.w*=inv;
        a3.x*=inv; a3.y*=inv; a3.z*=inv; a3.w*=inv;
        float4* orow = (float4*)(Ob + (size_t)(q0 + aq) * Dc);
        orow[ql +  0] = a0;
        orow[ql +  4] = a1;
        orow[ql +  8] = a2;
        orow[ql + 12] = a3;
    }
}

extern "C" void kernel_launch(void* const* d_in, const int* in_sizes, int n_in,
                              void* d_out, int out_size) {
    const float* Q  = (const float*)d_in[0];
    const float* K  = (const float*)d_in[1];
    const float* V  = (const float*)d_in[2];
    const void*  M  = d_in[3];               // bool mask — dtype detected on device
    const float* TW = (const float*)d_in[4];
    const float* DU = (const float*)d_in[5];
    float* O = (float*)d_out;

    const size_t smem_bytes =
        (size_t)(BQ * DPAD + 2 * BKT * DPAD + BQ * BKPAD + 3 * BQ) * sizeof(float);

    cudaFuncSetAttribute(attn_flash_kernel,
                         cudaFuncAttributeMaxDynamicSharedMemorySize,
                         (int)smem_bytes);

    // 1) Detect mask storage layout (word-bool vs byte-bool). Deterministic,
    //    graph-capturable, ~2us.
    detect_mask_dtype_kernel<<<1, 256>>>((const unsigned int*)M);

    // 2) Flash attention, one CTA per (b, h, q-tile).
    dim3 grid(Bc * Hc * (Sc / BQ));   // 1024 blocks
    attn_flash_kernel<<<grid, NTHREADS, smem_bytes>>>(Q, K, V, M, TW, DU, O);
}

// round 11
// speedup vs baseline: 1.0052x; 1.0052x over previous
#include <cuda_runtime.h>
#include <math.h>

// Shapes (fixed by the problem)
#define Bc 4
#define Hc 16
#define Sc 1024
#define Dc 64

// Tiling
#define BQ 64
#define BKT 64
#define DPAD 68      // 64 + 4 pad (floats) — float4-aligned rows, breaks bank patterns
#define BKPAD 68
#define NTHREADS 256

// Mask layout flag: 0 = 32-bit words (int32 or float32 bool), 1 = 1-byte bools
__device__ int g_mask_byte_mode;

__global__ void detect_mask_dtype_kernel(const unsigned int* __restrict__ m) {
    __shared__ int bad;
    if (threadIdx.x == 0) bad = 0;
    __syncthreads();
    // Scan 8192 words (32KB). Safe for any candidate layout (buffer >= 64MB).
    // int32 bools  -> words in {0,1}
    // float32 bools-> words in {0, 0x3F800000}
    // u8 bools     -> packed words like 0x01010101 appear w.p. 7/8 per word
    int local_bad = 0;
    for (int i = threadIdx.x; i < 8192; i += blockDim.x) {
        unsigned int w = m[i];
        if (w != 0u && w != 1u && w != 0x3F800000u) local_bad = 1;
    }
    if (local_bad) bad = 1;
    __syncthreads();
    if (threadIdx.x == 0) g_mask_byte_mode = bad;
}

__global__ __launch_bounds__(NTHREADS, 2)
void attn_flash_kernel(const float* __restrict__ Q,
                       const float* __restrict__ K,
                       const float* __restrict__ V,
                       const void* __restrict__ MSK,
                       const float* __restrict__ TW,
                       const float* __restrict__ DU,
                       float* __restrict__ O) {
    extern __shared__ float sm[];
    float* sQ = sm;                          // BQ  x DPAD
    float* sK = sQ + BQ * DPAD;              // BKT x DPAD
    float* sV = sK + BKT * DPAD;             // BKT x DPAD
    float* sP = sV + BKT * DPAD;             // BQ  x BKPAD (scores -> weights)
    float* sMx = sP + BQ * BKPAD;            // BQ running max
    float* sZ  = sMx + BQ;                   // BQ running denom
    float* sC  = sZ + BQ;                    // BQ correction factor

    const int t  = threadIdx.x;
    const int bh = blockIdx.x >> 4;          // Sc/BQ == 16 q-tiles
    const int qt = blockIdx.x & 15;
    const int q0 = qt * BQ;

    const int mask_bytes = g_mask_byte_mode; // uniform across grid

    const size_t qkvbase = (size_t)bh * Sc * Dc;
    const size_t mbase   = (size_t)bh * Sc * Sc;
    const float* Qb = Q + qkvbase;
    const float* Kb = K + qkvbase;
    const float* Vb = V + qkvbase;
    const unsigned int*  MbW = (const unsigned int*)MSK + mbase;   // word bools
    const unsigned char* MbB = (const unsigned char*)MSK + mbase;  // byte bools
    const float* Tb = TW + mbase;
    const float* Ub = DU + mbase;
    float* Ob = O + qkvbase;

    // ---- Load Q tile (coalesced float4) ----
    for (int i = t; i < BQ * (Dc / 4); i += NTHREADS) {
        int q = i >> 4, d4 = i & 15;
        ((float4*)(sQ + q * DPAD))[d4] =
            ((const float4*)(Qb + (size_t)(q0 + q) * Dc))[d4];
    }
    if (t < BQ) { sMx[t] = -INFINITY; sZ[t] = 0.f; }

    // Phase-D / epilogue thread mapping: thread owns query aq, float4 chunks
    // at d4 = ql + 4*i (interleaved -> conflict-free sV reads)
    const int aq = t >> 2;
    const int ql = t & 3;
    float4 a0 = make_float4(0.f, 0.f, 0.f, 0.f);
    float4 a1 = a0, a2 = a0, a3 = a0;

    // Phase-A mapping: 4x4 micro-tile, q rows tq..tq+3, k cols u+16j (striped)
    const int tq = (t >> 4) << 2;            // 0,4,...,60
    const int u  = t & 15;

    __syncthreads();

    const float scale = 0.125f;              // 1/sqrt(64)

    for (int kt = 0; kt < Sc / BKT; kt++) {
        const int k0 = kt * BKT;

        // ---- Load K,V tiles ----
        for (int i = t; i < BKT * (Dc / 4); i += NTHREADS) {
            int k = i >> 4, d4 = i & 15;
            ((float4*)(sK + k * DPAD))[d4] =
                ((const float4*)(Kb + (size_t)(k0 + k) * Dc))[d4];
            ((float4*)(sV + k * DPAD))[d4] =
                ((const float4*)(Vb + (size_t)(k0 + k) * Dc))[d4];
        }
        __syncthreads();

        // ---- Phase A: S = Q K^T (4x4 micro-tile per thread) ----
        {
            float s00=0,s01=0,s02=0,s03=0, s10=0,s11=0,s12=0,s13=0;
            float s20=0,s21=0,s22=0,s23=0, s30=0,s31=0,s32=0,s33=0;
            #pragma unroll 4
            for (int d4 = 0; d4 < 16; d4++) {
                float4 q0v = ((const float4*)(sQ + (tq + 0) * DPAD))[d4];
                float4 q1v = ((const float4*)(sQ + (tq + 1) * DPAD))[d4];
                float4 q2v = ((const float4*)(sQ + (tq + 2) * DPAD))[d4];
                float4 q3v = ((const float4*)(sQ + (tq + 3) * DPAD))[d4];
                float4 k0v = ((const float4*)(sK + (u +  0) * DPAD))[d4];
                float4 k1v = ((const float4*)(sK + (u + 16) * DPAD))[d4];
                float4 k2v = ((const float4*)(sK + (u + 32) * DPAD))[d4];
                float4 k3v = ((const float4*)(sK + (u + 48) * DPAD))[d4];
                s00 += q0v.x*k0v.x + q0v.y*k0v.y + q0v.z*k0v.z + q0v.w*k0v.w;
                s01 += q0v.x*k1v.x + q0v.y*k1v.y + q0v.z*k1v.z + q0v.w*k1v.w;
                s02 += q0v.x*k2v.x + q0v.y*k2v.y + q0v.z*k2v.z + q0v.w*k2v.w;
                s03 += q0v.x*k3v.x + q0v.y*k3v.y + q0v.z*k3v.z + q0v.w*k3v.w;
                s10 += q1v.x*k0v.x + q1v.y*k0v.y + q1v.z*k0v.z + q1v.w*k0v.w;
                s11 += q1v.x*k1v.x + q1v.y*k1v.y + q1v.z*k1v.z + q1v.w*k1v.w;
                s12 += q1v.x*k2v.x + q1v.y*k2v.y + q1v.z*k2v.z + q1v.w*k2v.w;
                s13 += q1v.x*k3v.x + q1v.y*k3v.y + q1v.z*k3v.z + q1v.w*k3v.w;
                s20 += q2v.x*k0v.x + q2v.y*k0v.y + q2v.z*k0v.z + q2v.w*k0v.w;
                s21 += q2v.x*k1v.x + q2v.y*k1v.y + q2v.z*k1v.z + q2v.w*k1v.w;
                s22 += q2v.x*k2v.x + q2v.y*k2v.y + q2v.z*k2v.z + q2v.w*k2v.w;
                s23 += q2v.x*k3v.x + q2v.y*k3v.y + q2v.z*k3v.z + q2v.w*k3v.w;
                s30 += q3v.x*k0v.x + q3v.y*k0v.y + q3v.z*k0v.z + q3v.w*k0v.w;
                s31 += q3v.x*k1v.x + q3v.y*k1v.y + q3v.z*k1v.z + q3v.w*k1v.w;
                s32 += q3v.x*k2v.x + q3v.y*k2v.y + q3v.z*k2v.z + q3v.w*k2v.w;
                s33 += q3v.x*k3v.x + q3v.y*k3v.y + q3v.z*k3v.z + q3v.w*k3v.w;
            }
            float sv[4][4] = {{s00,s01,s02,s03},{s10,s11,s12,s13},
                              {s20,s21,s22,s23},{s30,s31,s32,s33}};
            if (mask_bytes == 0) {
                // int32 / float32 bool: nonzero word == masked
                #pragma unroll
                for (int i = 0; i < 4; i++) {
                    const unsigned int* mrow = MbW + (size_t)(q0 + tq + i) * Sc + k0;
                    float* prow = sP + (tq + i) * BKPAD;
                    #pragma unroll
                    for (int j = 0; j < 4; j++) {
                        int k = u + 16 * j;
                        prow[k] = mrow[k] ? -1e9f : sv[i][j] * scale;
                    }
                }
            } else {
                // 1-byte bool
                #pragma unroll
                for (int i = 0; i < 4; i++) {
                    const unsigned char* mrow = MbB + (size_t)(q0 + tq + i) * Sc + k0;
                    float* prow = sP + (tq + i) * BKPAD;
                    #pragma unroll
                    for (int j = 0; j < 4; j++) {
                        int k = u + 16 * j;
                        prow[k] = mrow[k] ? -1e9f : sv[i][j] * scale;
                    }
                }
            }
        }
        __syncthreads();

        // ---- Phase B: per-row tile max, combine with running max ----
        {
            int r = t >> 2;
            float mx = -INFINITY;
            #pragma unroll
            for (int k = ql; k < BKT; k += 4) mx = fmaxf(mx, sP[r * BKPAD + k]);
            mx = fmaxf(mx, __shfl_xor_sync(0xffffffffu, mx, 1));
            mx = fmaxf(mx, __shfl_xor_sync(0xffffffffu, mx, 2));
            if (ql == 0) {
                float mold = sMx[r];
                float mnew = fmaxf(mold, mx);
                sMx[r] = mnew;
                sC[r]  = __expf(mold - mnew);   // 0 on first tile (mold=-inf)
            }
        }
        __syncthreads();

        // ---- Phase C: p=exp(s-m); Z update; fold tw * dropout into P ----
        // warp w owns rows 8w..8w+7; lanes stride k -> coalesced tw/du loads
        {
            int w = t >> 5, lane = t & 31;
            #pragma unroll
            for (int r8 = 0; r8 < 8; r8++) {
                int r = (w << 3) + r8;
                float mnew = sMx[r];
                const float* trow = Tb + (size_t)(q0 + r) * Sc + k0;
                const float* urow = Ub + (size_t)(q0 + r) * Sc + k0;
                float sum = 0.f;
                #pragma unroll
                for (int h = 0; h < 2; h++) {
                    int k = lane + 32 * h;
                    float p = __expf(sP[r * BKPAD + k] - mnew);
                    sum += p;
                    float keep = (urow[k] >= 0.5f) ? 2.0f : 0.0f;
                    sP[r * BKPAD + k] = p * trow[k] * keep;
                }
                #pragma unroll
                for (int off = 16; off; off >>= 1)
                    sum += __shfl_xor_sync(0xffffffffu, sum, off);
                if (lane == 0) sZ[r] = sZ[r] * sC[r] + sum;
            }
        }
        __syncthreads();

        // ---- Phase D: acc = acc*c + P_w @ V ----
        {
            float c = sC[aq];
            a0.x*=c; a0.y*=c; a0.z*=c; a0.w*=c;
            a1.x*=c; a1.y*=c; a1.z*=c; a1.w*=c;
            a2.x*=c; a2.y*=c; a2.z*=c; a2.w*=c;
            a3.x*=c; a3.y*=c; a3.z*=c; a3.w*=c;
            const float* prow = sP + aq * BKPAD;
            #pragma unroll 4
            for (int k = 0; k < BKT; k++) {
                float p = prow[k];
                const float4* vr = (const float4*)(sV + k * DPAD);
                float4 v;
                v = vr[ql +  0]; a0.x += p*v.x; a0.y += p*v.y; a0.z += p*v.z; a0.w += p*v.w;
                v = vr[ql +  4]; a1.x += p*v.x; a1.y += p*v.y; a1.z += p*v.z; a1.w += p*v.w;
                v = vr[ql +  8]; a2.x += p*v.x; a2.y += p*v.y; a2.z += p*v.z; a2.w += p*v.w;
                v = vr[ql + 12]; a3.x += p*v.x; a3.y += p*v.y; a3.z += p*v.z; a3.w += p*v.w;
            }
        }
        __syncthreads();
    }

    // ---- Epilogue: out = acc / Z ----
    {
        float inv = 1.0f / sZ[aq];
        a0.x*=inv; a0.y*=inv; a0.z*=inv; a0.w*=inv;
        a1.x*=inv; a1.y*=inv; a1.z*=inv; a1.w*=inv;
        a2.x*=inv; a2.y*=inv; a2.z*=inv; a2.w*=inv;
        a3.x*=inv; a3.y*=inv; a3.z*=inv; a3.w*=inv;
        float4* orow = (float4*)(Ob + (size_t)(q0 + aq) * Dc);
        orow[ql +  0] = a0;
        orow[ql +  4] = a1;
        orow[ql +  8] = a2;
        orow[ql + 12] = a3;
    }
}

extern "C" void kernel_launch(void* const* d_in, const int* in_sizes, int n_in,
                              void* d_out, int out_size) {
    const float* Q  = (const float*)d_in[0];
    const float* K  = (const float*)d_in[1];
    const float* V  = (const float*)d_in[2];
    const void*  M  = d_in[3];               // bool mask — dtype detected on device
    const float* TW = (const float*)d_in[4];
    const float* DU = (const float*)d_in[5];
    float* O = (float*)d_out;

    const size_t smem_bytes =
        (size_t)(BQ * DPAD + 2 * BKT * DPAD + BQ * BKPAD + 3 * BQ) * sizeof(float);

    cudaFuncSetAttribute(attn_flash_kernel,
                         cudaFuncAttributeMaxDynamicSharedMemorySize,
                         (int)smem_bytes);

    // 1) Detect mask storage layout (word-bool vs byte-bool). Deterministic,
    //    graph-capturable, ~2us.
    detect_mask_dtype_kernel<<<1, 256>>>((const unsigned int*)M);

    // 2) Flash attention, one CTA per (b, h, q-tile).
    dim3 grid(Bc * Hc * (Sc / BQ));   // 1024 blocks
    attn_flash_kernel<<<grid, NTHREADS, smem_bytes>>>(Q, K, V, M, TW, DU, O);
}